// round 12
// baseline (speedup 1.0000x reference)
#include <cuda_runtime.h>
#include <cuda_bf16.h>
#include <cstdint>
#include <math.h>

#define NB    4
#define NOBJ  135
#define NFEAT 540
#define ZD    64
#define HID   512
#define NOUT  12288   // 3*64*64
#define IMGW  128
#define OBJW  64
#define W2U4  (HID * NOUT / 8)     // 786432 uint4 units
#define W2THIRD (W2U4 / 3)         // 262144

// ================= scratch (device globals; no allocation allowed) =========
__device__ float4        g_candf[NB][NFEAT];   // ax, ay, 1/w, 1/h
__device__ int           g_candd[NB][NFEAT];
__device__ int           g_ncand[NB];
__device__ int           g_need[NB][NOBJ];
__device__ int           g_rows[640];
__device__ int           g_nrows;
__device__ __align__(16) __nv_bfloat16 g_hb[640][HID];    // hidden acts, bf16
__device__ __align__(16) __nv_bfloat16 g_W2b[HID * NOUT]; // W2 in bf16
__device__ __align__(16) float g_dec[NB*NOBJ][NOUT];
__device__ int           g_winner[NB][IMGW][IMGW];

__device__ __forceinline__ int recon_idx(int j) {
    if (j < 400) return j >> 2;
    if (j < 500) return 100 + ((j - 400) >> 2);
    if (j < 536) return 125 + ((j - 500) >> 2);
    return 134;
}
__device__ __forceinline__ uint32_t smem_u32(const void* p) {
    uint32_t a;
    asm("{ .reg .u64 t; cvta.to.shared.u64 t, %1; cvt.u32.u64 %0, t; }" : "=r"(a) : "l"(p));
    return a;
}
__device__ __forceinline__ uint32_t pkbf(float a, float b) {
    __nv_bfloat162 h = __floats2bfloat162_rn(a, b);
    return *(uint32_t*)&h;
}
__device__ __forceinline__ void cpasync16(uint32_t saddr, const void* g) {
    asm volatile("cp.async.cg.shared.global [%0], [%1], 16;" :: "r"(saddr), "l"(g));
}
#define CP_COMMIT() asm volatile("cp.async.commit_group;" ::: "memory")
#define CP_WAIT(N)  asm volatile("cp.async.wait_group %0;" :: "n"(N) : "memory")

// W2 fp32 -> bf16, one contiguous range of uint4 outputs
__device__ __forceinline__ void conv_w2(const float* __restrict__ W2,
                                        int cid, int nth, int lo, int cnt) {
    const float4* src = (const float4*)W2;
    uint4* dst = (uint4*)g_W2b;
    for (int o = lo + cid; o < lo + cnt; o += nth) {
        float4 f0 = src[o * 2], f1 = src[o * 2 + 1];
        uint4 v;
        v.x = pkbf(f0.x, f0.y);
        v.y = pkbf(f0.z, f0.w);
        v.z = pkbf(f1.x, f1.y);
        v.w = pkbf(f1.z, f1.w);
        dst[o] = v;
    }
}

// ---------------- K1: sort/candidates (blocks 0-3) + W2 conv 1/3 -----------
__global__ void k_sort(const float* __restrict__ zdepth,
                       const float* __restrict__ zwhere,
                       const int*   __restrict__ zpres,
                       const float* __restrict__ W2) {
    int t = threadIdx.x;   // 544

    if (blockIdx.x >= 4) {
        conv_w2(W2, (blockIdx.x - 4) * 544 + t, 384 * 544, 0, W2THIRD);
        return;
    }

    int b = blockIdx.x;
    __shared__ float sd[NFEAT];
    __shared__ int   sord[NFEAT];
    __shared__ int   swsum[17];

    if (b == 0 && t == 0) g_nrows = 0;
    if (t < NFEAT) sd[t] = zdepth[b * NOBJ + recon_idx(t)];
    if (t < NOBJ)  g_need[b][t] = 0;
    __syncthreads();

    if (t < NFEAT) {
        float dj = sd[t];
        int r = 0;
        for (int k = 0; k < NFEAT; k++) {
            float dk = sd[k];
            r += (dk > dj) || (dk == dj && k < t);   // stable, descending
        }
        sord[r] = t;
    }
    __syncthreads();

    int j    = (t < NFEAT) ? sord[t] : -1;
    int flag = (t < NFEAT) ? (zpres[b * NFEAT + j] != 0) : 0;
    unsigned bal = __ballot_sync(0xffffffffu, flag);
    int lane = t & 31, w = t >> 5;
    if (lane == 0) swsum[w] = __popc(bal);
    __syncthreads();
    int base = 0;
    for (int i = 0; i < w; i++) base += swsum[i];
    if (flag) {
        int pos = base + __popc(bal & ((1u << lane) - 1u));
        const float* zw = zwhere + (size_t)(b * NFEAT + j) * 4;
        float cx = zw[0], cy = zw[1], ww = zw[2], hh = zw[3];
        ww = fmaxf(ww, 0.01f);
        hh = fmaxf(hh, 0.01f);
        float4 f;
        f.x = 2.0f * cx - 1.0f;
        f.y = 2.0f * cy - 1.0f;
        f.z = 1.0f / ww;               // reciprocal: winner/sample use FMUL
        f.w = 1.0f / hh;
        g_candf[b][pos] = f;
        g_candd[b][pos] = recon_idx(j);
    }
    if (t == 0) {
        int s = 0;
        for (int i = 0; i < 17; i++) s += swsum[i];
        g_ncand[b] = s;
    }
}

// ---------------- K2: winner (blocks 0-255) + W2 conv 2/3 ------------------
__global__ void k_winner(const float* __restrict__ W2) {
    int t = threadIdx.x;
    if (blockIdx.x >= 256) {
        conv_w2(W2, (blockIdx.x - 256) * 256 + t, 384 * 256, W2THIRD, W2THIRD);
        return;
    }

    int blk = blockIdx.x;
    int b = blk >> 6;
    int ypair = blk & 63;
    int y = ypair * 2 + (t >> 7);
    int x = t & 127;

    __shared__ float4 cf[NFEAT];
    __shared__ int    cd[NFEAT];
    int nc = g_ncand[b];
    for (int i = t; i < nc; i += 256) { cf[i] = g_candf[b][i]; cd[i] = g_candd[b][i]; }
    __syncthreads();

    float gx = -1.0f + x * (2.0f / 127.0f);
    float gy = -1.0f + y * (2.0f / 127.0f);

    int win = -1;
    for (int s = 0; s < nc; s++) {
        float4 p = cf[s];
        float u = (gx - p.x) * p.z;
        float v = (gy - p.y) * p.w;
        float px = (u + 1.0f) * 0.5f * 63.0f;
        float py = (v + 1.0f) * 0.5f * 63.0f;
        float x0 = floorf(px), y0 = floorf(py);
        float wx = px - x0, wy = py - y0;
        int xi = (int)x0, yi = (int)y0;
        bool vx0 = (xi >= 0) && (xi < OBJW);
        bool vx1 = (xi + 1 >= 0) && (xi + 1 < OBJW);
        bool vy0 = (yi >= 0) && (yi < OBJW);
        bool vy1 = (yi + 1 >= 0) && (yi + 1 < OBJW);
        bool wxp = wx > 0.0f, wyp = wy > 0.0f;
        bool cov = (vy0 && vx0) || (vy0 && vx1 && wxp) ||
                   (vy1 && vx0 && wyp) || (vy1 && vx1 && wxp && wyp);
        if (cov) {
            win = s;
            int d = cd[s];
            if (g_need[b][d] == 0) {
                if (atomicExch(&g_need[b][d], 1) == 0) {
                    int slot = atomicAdd(&g_nrows, 1);
                    g_rows[slot] = b * NOBJ + d;
                }
            }
            break;
        }
    }
    g_winner[b][y][x] = win;
}

// ---------------- K3: hidden layer (mt<34) + W2 conv 3/3 -------------------
__global__ __launch_bounds__(256) void k_hidden(const float* __restrict__ zwhat,
                                                const float* __restrict__ W1,
                                                const float* __restrict__ b1,
                                                const float* __restrict__ W2) {
    int nt = blockIdx.x, mt = blockIdx.y;    // 4 x 130 (mt>=34 -> conversion)
    int t = threadIdx.x;
    if (mt >= 34) {
        conv_w2(W2, ((mt - 34) * 4 + nt) * 256 + t, 384 * 256, 2 * W2THIRD,
                W2U4 - 2 * W2THIRD);
        return;
    }

    __shared__ __align__(16) float sA[16][68];   // row stride 272 B (16-aligned)
    __shared__ __align__(16) float sW[64][132];
    int nrows = g_nrows;

    {   // A tile 16x64 = 256 float4
        int m = t >> 4, k4 = t & 15;
        int slot = mt * 16 + m;
        float4 v = make_float4(0.f, 0.f, 0.f, 0.f);
        if (slot < nrows) v = *(const float4*)&zwhat[(size_t)g_rows[slot] * ZD + k4 * 4];
        *(float4*)&sA[m][k4 * 4] = v;
    }
#pragma unroll
    for (int l = 0; l < 8; l++) {
        int id = t + l * 256;           // W tile 64x128 (2048 float4)
        int k = id >> 5, c4 = id & 31;
        float4 v = *(const float4*)&W1[(size_t)k * HID + nt * 128 + c4 * 4];
        *(float4*)&sW[k][c4 * 4] = v;
    }
    __syncthreads();

    int tm = t >> 5, tn = t & 31;       // rows tm*2.., cols tn*4..
    float acc[2][4];
#pragma unroll
    for (int i = 0; i < 2; i++)
#pragma unroll
        for (int j = 0; j < 4; j++) acc[i][j] = 0.0f;

#pragma unroll 8
    for (int k = 0; k < 64; k++) {
        float a[2], w[4];
#pragma unroll
        for (int i = 0; i < 2; i++) a[i] = sA[tm * 2 + i][k];
#pragma unroll
        for (int j = 0; j < 4; j++) w[j] = sW[k][tn * 4 + j];
#pragma unroll
        for (int i = 0; i < 2; i++)
#pragma unroll
            for (int j = 0; j < 4; j++) acc[i][j] = fmaf(a[i], w[j], acc[i][j]);
    }

#pragma unroll
    for (int i = 0; i < 2; i++) {
        int slot = mt * 16 + tm * 2 + i;
        int n = nt * 128 + tn * 4;
        float v0 = fmaxf(acc[i][0] + b1[n + 0], 0.0f);
        float v1 = fmaxf(acc[i][1] + b1[n + 1], 0.0f);
        float v2 = fmaxf(acc[i][2] + b1[n + 2], 0.0f);
        float v3 = fmaxf(acc[i][3] + b1[n + 3], 0.0f);
        uint2 pp;
        pp.x = pkbf(v0, v1);
        pp.y = pkbf(v2, v3);
        *(uint2*)&g_hb[slot][n] = pp;
    }
}

// ---------------- K4: HMMA bf16 GEMM 512 -> 12288 + bias + sigmoid ---------
// CTA 128x128, 16 warps (4M x 4N, warp tile 32x32), K-chunks of 64,
// 3-stage cp.async pipeline (105 KB smem), 8 barriers total.
#define ASTR2 144           // A row stride bytes (128 data + 16 pad, phase 9)
#define ASTB (128 * ASTR2)  // 18432
#define BSTB (64 * 272)     // 17408
#define NSTG 3
#define GEMM_DSMEM (NSTG * (ASTB + BSTB))   // 107520

__device__ __forceinline__ void ldsm4(uint32_t* r, uint32_t addr) {
    asm volatile("ldmatrix.sync.aligned.m8n8.x4.shared.b16 {%0,%1,%2,%3}, [%4];"
                 : "=r"(r[0]), "=r"(r[1]), "=r"(r[2]), "=r"(r[3]) : "r"(addr));
}
__device__ __forceinline__ void ldsm4t(uint32_t* r, uint32_t addr) {
    asm volatile("ldmatrix.sync.aligned.m8n8.x4.trans.shared.b16 {%0,%1,%2,%3}, [%4];"
                 : "=r"(r[0]), "=r"(r[1]), "=r"(r[2]), "=r"(r[3]) : "r"(addr));
}
__device__ __forceinline__ void mma16816(float* d, const uint32_t* a,
                                         uint32_t b0, uint32_t b1) {
    asm volatile("mma.sync.aligned.m16n8k16.row.col.f32.bf16.bf16.f32 "
                 "{%0,%1,%2,%3}, {%4,%5,%6,%7}, {%8,%9}, {%0,%1,%2,%3};"
                 : "+f"(d[0]), "+f"(d[1]), "+f"(d[2]), "+f"(d[3])
                 : "r"(a[0]), "r"(a[1]), "r"(a[2]), "r"(a[3]), "r"(b0), "r"(b1));
}

__global__ __launch_bounds__(512, 1) void k_gemm_mma(const float* __restrict__ b2) {
    int nrows = g_nrows;
    int mbase = blockIdx.y * 128;
    if (mbase >= nrows) return;
    int n0 = blockIdx.x * 128;

    extern __shared__ __align__(16) char dsm[];
    uint32_t smBase = smem_u32(dsm);

    int t = threadIdx.x, wid = t >> 5, lane = t & 31;
    int warpM = wid & 3, warpN = wid >> 2;      // 4 x 4, warp tile 32x32

    float acc[2][4][4];
#pragma unroll
    for (int mi = 0; mi < 2; mi++)
#pragma unroll
        for (int n8 = 0; n8 < 4; n8++)
#pragma unroll
            for (int r = 0; r < 4; r++) acc[mi][n8][r] = 0.0f;

    // per-thread cp.async slots: 2 A units + 2 B units per 64-K chunk
    int mA0 = t >> 3,         kqA0 = t & 7;          // A: 128 rows x 8 units
    int mA1 = (t + 512) >> 3, kqA1 = (t + 512) & 7;
    int kB0 = t >> 4,         cB0  = t & 15;         // B: 64 rows x 16 units
    int kB1 = (t + 512) >> 4, cB1  = (t + 512) & 15;

#define ISSUE_CHUNK(c, st) do {                                                  \
    int _k0 = (c) * 64;                                                          \
    uint32_t _aB = smBase + (st) * ASTB;                                         \
    uint32_t _bB = smBase + NSTG * ASTB + (st) * BSTB;                           \
    cpasync16(_aB + mA0 * ASTR2 + kqA0 * 16, &g_hb[mbase + mA0][_k0 + kqA0 * 8]);\
    cpasync16(_aB + mA1 * ASTR2 + kqA1 * 16, &g_hb[mbase + mA1][_k0 + kqA1 * 8]);\
    cpasync16(_bB + kB0 * 272 + cB0 * 16,                                        \
              &g_W2b[(size_t)(_k0 + kB0) * NOUT + n0 + cB0 * 8]);                \
    cpasync16(_bB + kB1 * 272 + cB1 * 16,                                        \
              &g_W2b[(size_t)(_k0 + kB1) * NOUT + n0 + cB1 * 8]);                \
    CP_COMMIT();                                                                 \
} while (0)

    ISSUE_CHUNK(0, 0);
    ISSUE_CHUNK(1, 1);

    for (int c = 0; c < 8; c++) {
        int st = c % 3;
        if (c < 6) CP_WAIT(1);       // chunk c landed (c+1 may be in flight)
        else       CP_WAIT(0);
        __syncthreads();             // all warps done consuming stage (c-1)%3
        if (c < 6) ISSUE_CHUNK(c + 2, (c + 2) % 3);

        uint32_t aB = smBase + st * ASTB;
        uint32_t bB = smBase + NSTG * ASTB + st * BSTB;

        // hoist A frags for this chunk (4 k-slices x 2 mi halves)
        uint32_t afr[4][2][4];
#pragma unroll
        for (int ks = 0; ks < 4; ks++)
#pragma unroll
            for (int mi = 0; mi < 2; mi++) {
                int row = warpM * 32 + mi * 16 + (lane & 15);
                ldsm4(afr[ks][mi], aB + row * ASTR2 + ks * 32 + (lane >> 4) * 16);
            }
#pragma unroll
        for (int ks = 0; ks < 4; ks++) {
#pragma unroll
            for (int cg = 0; cg < 2; cg++) {     // two 16-col groups
                uint32_t bfr[4];
                int krow = ks * 16 + (lane & 15);
                ldsm4t(bfr, bB + krow * 272 + (warpN * 32 + cg * 16) * 2 + (lane >> 4) * 16);
#pragma unroll
                for (int mi = 0; mi < 2; mi++) {
                    mma16816(acc[mi][cg * 2 + 0], afr[ks][mi], bfr[0], bfr[1]);
                    mma16816(acc[mi][cg * 2 + 1], afr[ks][mi], bfr[2], bfr[3]);
                }
            }
        }
    }

    // ---- epilogue: bias + sigmoid, store via d-frag mapping
    int p = lane >> 2, q = lane & 3;
#pragma unroll
    for (int mi = 0; mi < 2; mi++) {
#pragma unroll
        for (int half = 0; half < 2; half++) {
            int slot = mbase + warpM * 32 + mi * 16 + p + half * 8;
            if (slot < nrows) {
                int row = g_rows[slot];
#pragma unroll
                for (int n8 = 0; n8 < 4; n8++) {
                    int col = n0 + warpN * 32 + n8 * 8 + q * 2;
                    float2 bb = *(const float2*)&b2[col];
                    float v0 = acc[mi][n8][half * 2 + 0] + bb.x;
                    float v1 = acc[mi][n8][half * 2 + 1] + bb.y;
                    float2 o;
                    o.x = 1.0f / (1.0f + __expf(-v0));
                    o.y = 1.0f / (1.0f + __expf(-v1));
                    *(float2*)&g_dec[row][col] = o;
                }
            }
        }
    }
}

// ---------------- K5: final bilinear sample + composite --------------------
__global__ void k_sample(float* __restrict__ out) {
    int id = blockIdx.x * 256 + threadIdx.x;
    int b = id >> 14;
    int y = (id >> 7) & 127;
    int x = id & 127;
    int s = g_winner[b][y][x];

    float val[3] = {0.0f, 0.0f, 0.0f};
    if (s >= 0) {
        float4 p = g_candf[b][s];
        int dec = g_candd[b][s];
        float gx = -1.0f + x * (2.0f / 127.0f);
        float gy = -1.0f + y * (2.0f / 127.0f);
        float u = (gx - p.x) * p.z;
        float v = (gy - p.y) * p.w;
        float px = (u + 1.0f) * 0.5f * 63.0f;
        float py = (v + 1.0f) * 0.5f * 63.0f;
        float x0 = floorf(px), y0 = floorf(py);
        float wx = px - x0, wy = py - y0;
        int xi = (int)x0, yi = (int)y0;
        bool vx0 = (xi >= 0) && (xi < OBJW);
        bool vx1 = (xi + 1 >= 0) && (xi + 1 < OBJW);
        bool vy0 = (yi >= 0) && (yi < OBJW);
        bool vy1 = (yi + 1 >= 0) && (yi + 1 < OBJW);
        float w00 = (vy0 && vx0) ? (1.0f - wy) * (1.0f - wx) : 0.0f;
        float w01 = (vy0 && vx1) ? (1.0f - wy) * wx : 0.0f;
        float w10 = (vy1 && vx0) ? wy * (1.0f - wx) : 0.0f;
        float w11 = (vy1 && vx1) ? wy * wx : 0.0f;
        int xc0 = min(max(xi, 0), 63),     xc1 = min(max(xi + 1, 0), 63);
        int yc0 = min(max(yi, 0), 63),     yc1 = min(max(yi + 1, 0), 63);
        const float* base = g_dec[b * NOBJ + dec];
#pragma unroll
        for (int c = 0; c < 3; c++) {
            const float* im = base + c * (OBJW * OBJW);
            val[c] = im[yc0 * OBJW + xc0] * w00 + im[yc0 * OBJW + xc1] * w01 +
                     im[yc1 * OBJW + xc0] * w10 + im[yc1 * OBJW + xc1] * w11;
        }
    }
#pragma unroll
    for (int c = 0; c < 3; c++)
        out[(((size_t)b * 3 + c) * IMGW + y) * IMGW + x] = val[c];
}

// ---------------------------------------------------------------------------
extern "C" void kernel_launch(void* const* d_in, const int* in_sizes, int n_in,
                              void* d_out, int out_size) {
    const float* z_what    = (const float*)d_in[0];
    const float* z_where   = (const float*)d_in[1];
    const float* z_depth   = (const float*)d_in[2];
    const float* W1        = (const float*)d_in[3];
    const float* b1        = (const float*)d_in[4];
    const float* W2        = (const float*)d_in[5];
    const float* b2        = (const float*)d_in[6];
    const int*   z_present = (const int*)d_in[7];
    float* out = (float*)d_out;

    static int attr_done = 0;
    if (!attr_done) {
        cudaFuncSetAttribute(k_gemm_mma,
                             cudaFuncAttributeMaxDynamicSharedMemorySize, GEMM_DSMEM);
        attr_done = 1;
    }

    k_sort<<<4 + 384, 544>>>(z_depth, z_where, z_present, W2);
    k_winner<<<640, 256>>>(W2);
    k_hidden<<<dim3(4, 130), 256>>>(z_what, W1, b1, W2);
    k_gemm_mma<<<dim3(96, 5), 512, GEMM_DSMEM>>>(b2);
    k_sample<<<256, 256>>>(out);
}

// round 13
// speedup vs baseline: 1.0934x; 1.0934x over previous
#include <cuda_runtime.h>
#include <cuda_bf16.h>
#include <cstdint>
#include <math.h>

#define NB    4
#define NOBJ  135
#define NFEAT 540
#define ZD    64
#define HID   512
#define NOUT  12288   // 3*64*64
#define IMGW  128
#define OBJW  64
#define W2U4  (HID * NOUT / 8)     // 786432 uint4 units

// ================= scratch (device globals; no allocation allowed) =========
__device__ float4        g_candf[NB][NFEAT];   // ax, ay, 1/w, 1/h
__device__ int           g_candd[NB][NFEAT];
__device__ int           g_ncand[NB];
__device__ int           g_need[NB][NOBJ];
__device__ int           g_rows[640];
__device__ int           g_nrows;
__device__ __align__(16) __nv_bfloat16 g_hb[640][HID];    // hidden acts, bf16
__device__ __align__(16) __nv_bfloat16 g_W2b[HID * NOUT]; // W2 in bf16
__device__ __align__(16) float g_dec[NB*NOBJ][NOUT];
__device__ int           g_winner[NB][IMGW][IMGW];

__device__ __forceinline__ int recon_idx(int j) {
    if (j < 400) return j >> 2;
    if (j < 500) return 100 + ((j - 400) >> 2);
    if (j < 536) return 125 + ((j - 500) >> 2);
    return 134;
}
__device__ __forceinline__ uint32_t smem_u32(const void* p) {
    uint32_t a;
    asm("{ .reg .u64 t; cvta.to.shared.u64 t, %1; cvt.u32.u64 %0, t; }" : "=r"(a) : "l"(p));
    return a;
}
__device__ __forceinline__ uint32_t pkbf(float a, float b) {
    __nv_bfloat162 h = __floats2bfloat162_rn(a, b);
    return *(uint32_t*)&h;
}
__device__ __forceinline__ void cpasync16(uint32_t saddr, const void* g) {
    asm volatile("cp.async.cg.shared.global [%0], [%1], 16;" :: "r"(saddr), "l"(g));
}
#define CP_COMMIT() asm volatile("cp.async.commit_group;" ::: "memory")
#define CP_WAIT(N)  asm volatile("cp.async.wait_group %0;" :: "n"(N) : "memory")

// ---------------- K1: sort/candidates (blocks 0-3) + full W2->bf16 ---------
__global__ void k_sort(const float* __restrict__ zdepth,
                       const float* __restrict__ zwhere,
                       const int*   __restrict__ zpres,
                       const float* __restrict__ W2) {
    int t = threadIdx.x;   // 544

    if (blockIdx.x >= 4) {
        // W2 fp32 -> bf16 conversion, grid-stride over uint4 outputs
        int cid = (blockIdx.x - 4) * 544 + t;
        const float4* src = (const float4*)W2;
        uint4* dst = (uint4*)g_W2b;
        for (int o = cid; o < W2U4; o += 1024 * 544) {
            float4 f0 = src[o * 2], f1 = src[o * 2 + 1];
            uint4 v;
            v.x = pkbf(f0.x, f0.y);
            v.y = pkbf(f0.z, f0.w);
            v.z = pkbf(f1.x, f1.y);
            v.w = pkbf(f1.z, f1.w);
            dst[o] = v;
        }
        return;
    }

    int b = blockIdx.x;
    __shared__ float sd[NFEAT];
    __shared__ int   sord[NFEAT];
    __shared__ int   swsum[17];

    if (b == 0 && t == 0) g_nrows = 0;
    if (t < NFEAT) sd[t] = zdepth[b * NOBJ + recon_idx(t)];
    if (t < NOBJ)  g_need[b][t] = 0;
    __syncthreads();

    if (t < NFEAT) {
        float dj = sd[t];
        int r = 0;
        for (int k = 0; k < NFEAT; k++) {
            float dk = sd[k];
            r += (dk > dj) || (dk == dj && k < t);   // stable, descending
        }
        sord[r] = t;
    }
    __syncthreads();

    int j    = (t < NFEAT) ? sord[t] : -1;
    int flag = (t < NFEAT) ? (zpres[b * NFEAT + j] != 0) : 0;
    unsigned bal = __ballot_sync(0xffffffffu, flag);
    int lane = t & 31, w = t >> 5;
    if (lane == 0) swsum[w] = __popc(bal);
    __syncthreads();
    int base = 0;
    for (int i = 0; i < w; i++) base += swsum[i];
    if (flag) {
        int pos = base + __popc(bal & ((1u << lane) - 1u));
        const float* zw = zwhere + (size_t)(b * NFEAT + j) * 4;
        float cx = zw[0], cy = zw[1], ww = zw[2], hh = zw[3];
        ww = fmaxf(ww, 0.01f);
        hh = fmaxf(hh, 0.01f);
        float4 f;
        f.x = 2.0f * cx - 1.0f;
        f.y = 2.0f * cy - 1.0f;
        f.z = 1.0f / ww;               // reciprocal: winner/sample use FMUL
        f.w = 1.0f / hh;
        g_candf[b][pos] = f;
        g_candd[b][pos] = recon_idx(j);
    }
    if (t == 0) {
        int s = 0;
        for (int i = 0; i < 17; i++) s += swsum[i];
        g_ncand[b] = s;
    }
}

// ---------------- K2: per-pixel winner + inline need-compaction ------------
__global__ void k_winner() {
    int blk = blockIdx.x;
    int b = blk >> 6;
    int ypair = blk & 63;
    int t = threadIdx.x;
    int y = ypair * 2 + (t >> 7);
    int x = t & 127;

    __shared__ float4 cf[NFEAT];
    __shared__ int    cd[NFEAT];
    int nc = g_ncand[b];
    for (int i = t; i < nc; i += 256) { cf[i] = g_candf[b][i]; cd[i] = g_candd[b][i]; }
    __syncthreads();

    float gx = -1.0f + x * (2.0f / 127.0f);
    float gy = -1.0f + y * (2.0f / 127.0f);

    int win = -1;
    for (int s = 0; s < nc; s++) {
        float4 p = cf[s];
        float u = (gx - p.x) * p.z;
        float v = (gy - p.y) * p.w;
        float px = (u + 1.0f) * 0.5f * 63.0f;
        float py = (v + 1.0f) * 0.5f * 63.0f;
        float x0 = floorf(px), y0 = floorf(py);
        float wx = px - x0, wy = py - y0;
        int xi = (int)x0, yi = (int)y0;
        bool vx0 = (xi >= 0) && (xi < OBJW);
        bool vx1 = (xi + 1 >= 0) && (xi + 1 < OBJW);
        bool vy0 = (yi >= 0) && (yi < OBJW);
        bool vy1 = (yi + 1 >= 0) && (yi + 1 < OBJW);
        bool wxp = wx > 0.0f, wyp = wy > 0.0f;
        bool cov = (vy0 && vx0) || (vy0 && vx1 && wxp) ||
                   (vy1 && vx0 && wyp) || (vy1 && vx1 && wxp && wyp);
        if (cov) {
            win = s;
            int d = cd[s];
            if (g_need[b][d] == 0) {
                if (atomicExch(&g_need[b][d], 1) == 0) {
                    int slot = atomicAdd(&g_nrows, 1);
                    g_rows[slot] = b * NOBJ + d;
                }
            }
            break;
        }
    }
    g_winner[b][y][x] = win;
}

// ---------------- K3: hidden layer 64->512 relu, tiled, bf16 out -----------
__global__ __launch_bounds__(256) void k_hidden(const float* __restrict__ zwhat,
                                                const float* __restrict__ W1,
                                                const float* __restrict__ b1) {
    __shared__ __align__(16) float sA[16][68];   // row stride 272 B (16-aligned)
    __shared__ __align__(16) float sW[64][132];
    int nt = blockIdx.x, mt = blockIdx.y;    // 4 x 34
    int nrows = g_nrows;
    int t = threadIdx.x;

    {   // A tile 16x64 = 256 float4
        int m = t >> 4, k4 = t & 15;
        int slot = mt * 16 + m;
        float4 v = make_float4(0.f, 0.f, 0.f, 0.f);
        if (slot < nrows) v = *(const float4*)&zwhat[(size_t)g_rows[slot] * ZD + k4 * 4];
        *(float4*)&sA[m][k4 * 4] = v;
    }
#pragma unroll
    for (int l = 0; l < 8; l++) {
        int id = t + l * 256;           // W tile 64x128 (2048 float4)
        int k = id >> 5, c4 = id & 31;
        float4 v = *(const float4*)&W1[(size_t)k * HID + nt * 128 + c4 * 4];
        *(float4*)&sW[k][c4 * 4] = v;
    }
    __syncthreads();

    int tm = t >> 5, tn = t & 31;       // rows tm*2.., cols tn*4..
    float acc[2][4];
#pragma unroll
    for (int i = 0; i < 2; i++)
#pragma unroll
        for (int j = 0; j < 4; j++) acc[i][j] = 0.0f;

#pragma unroll 8
    for (int k = 0; k < 64; k++) {
        float a[2], w[4];
#pragma unroll
        for (int i = 0; i < 2; i++) a[i] = sA[tm * 2 + i][k];
#pragma unroll
        for (int j = 0; j < 4; j++) w[j] = sW[k][tn * 4 + j];
#pragma unroll
        for (int i = 0; i < 2; i++)
#pragma unroll
            for (int j = 0; j < 4; j++) acc[i][j] = fmaf(a[i], w[j], acc[i][j]);
    }

#pragma unroll
    for (int i = 0; i < 2; i++) {
        int slot = mt * 16 + tm * 2 + i;
        int n = nt * 128 + tn * 4;
        float v0 = fmaxf(acc[i][0] + b1[n + 0], 0.0f);
        float v1 = fmaxf(acc[i][1] + b1[n + 1], 0.0f);
        float v2 = fmaxf(acc[i][2] + b1[n + 2], 0.0f);
        float v3 = fmaxf(acc[i][3] + b1[n + 3], 0.0f);
        uint2 pp;
        pp.x = pkbf(v0, v1);
        pp.y = pkbf(v2, v3);
        *(uint2*)&g_hb[slot][n] = pp;
    }
}

// ---------------- K4: HMMA bf16 GEMM 512 -> 12288 + bias + sigmoid ---------
// CTA 128x128, 16 warps (4M x 4N, warp tile 32x32), K-chunks of 64,
// 3-stage cp.async pipeline (105 KB smem), 8 barriers total.
#define ASTR2 144           // A row stride bytes (128 data + 16 pad, phase 9)
#define ASTB (128 * ASTR2)  // 18432
#define BSTB (64 * 272)     // 17408
#define NSTG 3
#define GEMM_DSMEM (NSTG * (ASTB + BSTB))   // 107520

__device__ __forceinline__ void ldsm4(uint32_t* r, uint32_t addr) {
    asm volatile("ldmatrix.sync.aligned.m8n8.x4.shared.b16 {%0,%1,%2,%3}, [%4];"
                 : "=r"(r[0]), "=r"(r[1]), "=r"(r[2]), "=r"(r[3]) : "r"(addr));
}
__device__ __forceinline__ void ldsm4t(uint32_t* r, uint32_t addr) {
    asm volatile("ldmatrix.sync.aligned.m8n8.x4.trans.shared.b16 {%0,%1,%2,%3}, [%4];"
                 : "=r"(r[0]), "=r"(r[1]), "=r"(r[2]), "=r"(r[3]) : "r"(addr));
}
__device__ __forceinline__ void mma16816(float* d, const uint32_t* a,
                                         uint32_t b0, uint32_t b1) {
    asm volatile("mma.sync.aligned.m16n8k16.row.col.f32.bf16.bf16.f32 "
                 "{%0,%1,%2,%3}, {%4,%5,%6,%7}, {%8,%9}, {%0,%1,%2,%3};"
                 : "+f"(d[0]), "+f"(d[1]), "+f"(d[2]), "+f"(d[3])
                 : "r"(a[0]), "r"(a[1]), "r"(a[2]), "r"(a[3]), "r"(b0), "r"(b1));
}

__global__ __launch_bounds__(512, 1) void k_gemm_mma(const float* __restrict__ b2) {
    int nrows = g_nrows;
    int mbase = blockIdx.y * 128;
    if (mbase >= nrows) return;
    int n0 = blockIdx.x * 128;

    extern __shared__ __align__(16) char dsm[];
    uint32_t smBase = smem_u32(dsm);

    int t = threadIdx.x, wid = t >> 5, lane = t & 31;
    int warpM = wid & 3, warpN = wid >> 2;      // 4 x 4, warp tile 32x32

    float acc[2][4][4];
#pragma unroll
    for (int mi = 0; mi < 2; mi++)
#pragma unroll
        for (int n8 = 0; n8 < 4; n8++)
#pragma unroll
            for (int r = 0; r < 4; r++) acc[mi][n8][r] = 0.0f;

    // per-thread cp.async slots: 2 A units + 2 B units per 64-K chunk
    int mA0 = t >> 3,         kqA0 = t & 7;          // A: 128 rows x 8 units
    int mA1 = (t + 512) >> 3, kqA1 = (t + 512) & 7;
    int kB0 = t >> 4,         cB0  = t & 15;         // B: 64 rows x 16 units
    int kB1 = (t + 512) >> 4, cB1  = (t + 512) & 15;

#define ISSUE_CHUNK(c, st) do {                                                  \
    int _k0 = (c) * 64;                                                          \
    uint32_t _aB = smBase + (st) * ASTB;                                         \
    uint32_t _bB = smBase + NSTG * ASTB + (st) * BSTB;                           \
    cpasync16(_aB + mA0 * ASTR2 + kqA0 * 16, &g_hb[mbase + mA0][_k0 + kqA0 * 8]);\
    cpasync16(_aB + mA1 * ASTR2 + kqA1 * 16, &g_hb[mbase + mA1][_k0 + kqA1 * 8]);\
    cpasync16(_bB + kB0 * 272 + cB0 * 16,                                        \
              &g_W2b[(size_t)(_k0 + kB0) * NOUT + n0 + cB0 * 8]);                \
    cpasync16(_bB + kB1 * 272 + cB1 * 16,                                        \
              &g_W2b[(size_t)(_k0 + kB1) * NOUT + n0 + cB1 * 8]);                \
    CP_COMMIT();                                                                 \
} while (0)

    ISSUE_CHUNK(0, 0);
    ISSUE_CHUNK(1, 1);

    for (int c = 0; c < 8; c++) {
        int st = c % 3;
        if (c < 6) CP_WAIT(1);       // chunk c landed (c+1 may be in flight)
        else       CP_WAIT(0);
        __syncthreads();             // all warps done consuming stage (c-1)%3
        if (c < 6) ISSUE_CHUNK(c + 2, (c + 2) % 3);

        uint32_t aB = smBase + st * ASTB;
        uint32_t bB = smBase + NSTG * ASTB + st * BSTB;

        // hoist A frags for this chunk (4 k-slices x 2 mi halves)
        uint32_t afr[4][2][4];
#pragma unroll
        for (int ks = 0; ks < 4; ks++)
#pragma unroll
            for (int mi = 0; mi < 2; mi++) {
                int row = warpM * 32 + mi * 16 + (lane & 15);
                ldsm4(afr[ks][mi], aB + row * ASTR2 + ks * 32 + (lane >> 4) * 16);
            }
#pragma unroll
        for (int ks = 0; ks < 4; ks++) {
#pragma unroll
            for (int cg = 0; cg < 2; cg++) {     // two 16-col groups
                uint32_t bfr[4];
                int krow = ks * 16 + (lane & 15);
                ldsm4t(bfr, bB + krow * 272 + (warpN * 32 + cg * 16) * 2 + (lane >> 4) * 16);
#pragma unroll
                for (int mi = 0; mi < 2; mi++) {
                    mma16816(acc[mi][cg * 2 + 0], afr[ks][mi], bfr[0], bfr[1]);
                    mma16816(acc[mi][cg * 2 + 1], afr[ks][mi], bfr[2], bfr[3]);
                }
            }
        }
    }

    // ---- epilogue: bias + sigmoid, store via d-frag mapping
    int p = lane >> 2, q = lane & 3;
#pragma unroll
    for (int mi = 0; mi < 2; mi++) {
#pragma unroll
        for (int half = 0; half < 2; half++) {
            int slot = mbase + warpM * 32 + mi * 16 + p + half * 8;
            if (slot < nrows) {
                int row = g_rows[slot];
#pragma unroll
                for (int n8 = 0; n8 < 4; n8++) {
                    int col = n0 + warpN * 32 + n8 * 8 + q * 2;
                    float2 bb = *(const float2*)&b2[col];
                    float v0 = acc[mi][n8][half * 2 + 0] + bb.x;
                    float v1 = acc[mi][n8][half * 2 + 1] + bb.y;
                    float2 o;
                    o.x = 1.0f / (1.0f + __expf(-v0));
                    o.y = 1.0f / (1.0f + __expf(-v1));
                    *(float2*)&g_dec[row][col] = o;
                }
            }
        }
    }
}

// ---------------- K5: final bilinear sample + composite --------------------
__global__ void k_sample(float* __restrict__ out) {
    int id = blockIdx.x * 256 + threadIdx.x;
    int b = id >> 14;
    int y = (id >> 7) & 127;
    int x = id & 127;
    int s = g_winner[b][y][x];

    float val[3] = {0.0f, 0.0f, 0.0f};
    if (s >= 0) {
        float4 p = g_candf[b][s];
        int dec = g_candd[b][s];
        float gx = -1.0f + x * (2.0f / 127.0f);
        float gy = -1.0f + y * (2.0f / 127.0f);
        float u = (gx - p.x) * p.z;
        float v = (gy - p.y) * p.w;
        float px = (u + 1.0f) * 0.5f * 63.0f;
        float py = (v + 1.0f) * 0.5f * 63.0f;
        float x0 = floorf(px), y0 = floorf(py);
        float wx = px - x0, wy = py - y0;
        int xi = (int)x0, yi = (int)y0;
        bool vx0 = (xi >= 0) && (xi < OBJW);
        bool vx1 = (xi + 1 >= 0) && (xi + 1 < OBJW);
        bool vy0 = (yi >= 0) && (yi < OBJW);
        bool vy1 = (yi + 1 >= 0) && (yi + 1 < OBJW);
        float w00 = (vy0 && vx0) ? (1.0f - wy) * (1.0f - wx) : 0.0f;
        float w01 = (vy0 && vx1) ? (1.0f - wy) * wx : 0.0f;
        float w10 = (vy1 && vx0) ? wy * (1.0f - wx) : 0.0f;
        float w11 = (vy1 && vx1) ? wy * wx : 0.0f;
        int xc0 = min(max(xi, 0), 63),     xc1 = min(max(xi + 1, 0), 63);
        int yc0 = min(max(yi, 0), 63),     yc1 = min(max(yi + 1, 0), 63);
        const float* base = g_dec[b * NOBJ + dec];
#pragma unroll
        for (int c = 0; c < 3; c++) {
            const float* im = base + c * (OBJW * OBJW);
            val[c] = im[yc0 * OBJW + xc0] * w00 + im[yc0 * OBJW + xc1] * w01 +
                     im[yc1 * OBJW + xc0] * w10 + im[yc1 * OBJW + xc1] * w11;
        }
    }
#pragma unroll
    for (int c = 0; c < 3; c++)
        out[(((size_t)b * 3 + c) * IMGW + y) * IMGW + x] = val[c];
}

// ---------------------------------------------------------------------------
extern "C" void kernel_launch(void* const* d_in, const int* in_sizes, int n_in,
                              void* d_out, int out_size) {
    const float* z_what    = (const float*)d_in[0];
    const float* z_where   = (const float*)d_in[1];
    const float* z_depth   = (const float*)d_in[2];
    const float* W1        = (const float*)d_in[3];
    const float* b1        = (const float*)d_in[4];
    const float* W2        = (const float*)d_in[5];
    const float* b2        = (const float*)d_in[6];
    const int*   z_present = (const int*)d_in[7];
    float* out = (float*)d_out;

    static int attr_done = 0;
    if (!attr_done) {
        cudaFuncSetAttribute(k_gemm_mma,
                             cudaFuncAttributeMaxDynamicSharedMemorySize, GEMM_DSMEM);
        attr_done = 1;
    }

    k_sort<<<4 + 1024, 544>>>(z_depth, z_where, z_present, W2);
    k_winner<<<256, 256>>>();
    k_hidden<<<dim3(4, 34), 256>>>(z_what, W1, b1);
    k_gemm_mma<<<dim3(96, 5), 512, GEMM_DSMEM>>>(b2);
    k_sample<<<256, 256>>>(out);
}